// round 6
// baseline (speedup 1.0000x reference)
#include <cuda_runtime.h>

// Problem shape (fixed for this instance)
#define B_ 64
#define S_ 1024
#define L_ 16
#define T_ 32
#define AROW 20            // padded row stride (floats) for the 16x16 matrices
#define MSLOT (AROW * 16)  // 320 floats per matrix slot

#define LOG2E 1.4426950408889634f
#define LN2   0.6931471805599453f

// Scratch (static __device__ arrays — allocation-free per harness rules)
__device__ __align__(16) float g_P   [B_ * 8 * 256];   // 128-step chunk matrices
__device__ __align__(16) float g_A0t [B_ * 8 * 256];   // level-0 matrices of the tail chunk
__device__ __align__(16) float g_tailw[B_ * 256];      // raw w rows for the <16-step tail
__device__             float g_nump[B_ * 8];           // per-(b,chunk) numerator partials
__device__             int   g_CP  [B_ * 8];           // chunk scale exponents
__device__             int   g_C0t [B_ * 8];           // tail-chunk level-0 exponents

__device__ __forceinline__ float ex2f_(float x) {
    float r; asm("ex2.approx.f32 %0, %1;" : "=f"(r) : "f"(x)); return r;
}
__device__ __forceinline__ float lg2f_(float x) {
    float r; asm("lg2.approx.f32 %0, %1;" : "=f"(r) : "f"(x)); return r;
}
__device__ __forceinline__ int clampd_(int d) {
    return d < -120 ? -120 : (d > 120 ? 120 : d);
}
__device__ __forceinline__ int expo_(float x) {
    return (__float_as_int(x) >> 23) & 255;
}

// ---------------------------------------------------------------------------
// 16x16 matrix product D = Am * Bm, one column (hl) per 16-lane group.
// Row-major, row stride AROW. Result max-normalized to ~2^0. D may alias Bm.
// ---------------------------------------------------------------------------
__device__ __forceinline__ void matmul16(
    const float* Am, const float* Bm, float* Dst,
    int Ca, int Cb, int* Cdst, int hl)
{
    float bc[16];
#pragma unroll
    for (int k = 0; k < 16; k++) bc[k] = Bm[k * AROW + hl];

    float r[16];
#pragma unroll
    for (int i = 0; i < 16; i++) {
        const float4* ar = reinterpret_cast<const float4*>(Am + i * AROW);
        float4 a0 = ar[0], a1 = ar[1], a2 = ar[2], a3 = ar[3];
        float s0 = a0.x * bc[0];
        s0 = fmaf(a0.y, bc[1], s0); s0 = fmaf(a0.z, bc[2], s0); s0 = fmaf(a0.w, bc[3], s0);
        float s1 = a1.x * bc[4];
        s1 = fmaf(a1.y, bc[5], s1); s1 = fmaf(a1.z, bc[6], s1); s1 = fmaf(a1.w, bc[7], s1);
        float s2 = a2.x * bc[8];
        s2 = fmaf(a2.y, bc[9], s2); s2 = fmaf(a2.z, bc[10], s2); s2 = fmaf(a2.w, bc[11], s2);
        float s3 = a3.x * bc[12];
        s3 = fmaf(a3.y, bc[13], s3); s3 = fmaf(a3.z, bc[14], s3); s3 = fmaf(a3.w, bc[15], s3);
        r[i] = (s0 + s1) + (s2 + s3);
    }

    int ex = 0;
#pragma unroll
    for (int i = 0; i < 16; i++) ex = max(ex, expo_(r[i]));
    ex = max(ex, __shfl_xor_sync(0xffffffffu, ex, 1, 16));
    ex = max(ex, __shfl_xor_sync(0xffffffffu, ex, 2, 16));
    ex = max(ex, __shfl_xor_sync(0xffffffffu, ex, 4, 16));
    ex = max(ex, __shfl_xor_sync(0xffffffffu, ex, 8, 16));
    int d = clampd_(ex - 127);
    float sc = __int_as_float((127 - d) << 23);
#pragma unroll
    for (int i = 0; i < 16; i++) Dst[i * AROW + hl] = r[i] * sc;
    if (hl == 0) *Cdst = Ca + Cb + d;
}

// Serial matvec: vf <- normalize(M * vf); row hl per lane, vf replicated on
// all 32 lanes (halves mirror via width-16 shfl).
__device__ __forceinline__ void matvec16(
    const float* __restrict__ M, int Cm, float* vf, int& Cv, int hl)
{
    const float4* rp = reinterpret_cast<const float4*>(M + hl * AROW);
    float4 c0 = rp[0], c1 = rp[1], c2 = rp[2], c3 = rp[3];
    float a0 = c0.x * vf[0];
    a0 = fmaf(c0.y, vf[1], a0); a0 = fmaf(c0.z, vf[2], a0); a0 = fmaf(c0.w, vf[3], a0);
    float a1 = c1.x * vf[4];
    a1 = fmaf(c1.y, vf[5], a1); a1 = fmaf(c1.z, vf[6], a1); a1 = fmaf(c1.w, vf[7], a1);
    float a2 = c2.x * vf[8];
    a2 = fmaf(c2.y, vf[9], a2); a2 = fmaf(c2.z, vf[10], a2); a2 = fmaf(c2.w, vf[11], a2);
    float a3 = c3.x * vf[12];
    a3 = fmaf(c3.y, vf[13], a3); a3 = fmaf(c3.z, vf[14], a3); a3 = fmaf(c3.w, vf[15], a3);
    float s = (a0 + a1) + (a2 + a3);
#pragma unroll
    for (int k = 0; k < 16; k++) vf[k] = __shfl_sync(0xffffffffu, s, k, 16);
    int ex = 0;
#pragma unroll
    for (int k = 0; k < 16; k++) ex = max(ex, expo_(vf[k]));
    int d = clampd_(ex - 127);
    Cv += d + Cm;
    float sc = __int_as_float((127 - d) << 23);
#pragma unroll
    for (int k = 0; k < 16; k++) vf[k] *= sc;
}

// ---------------------------------------------------------------------------
// Kernel FUSED: 512 blocks (64 batches x 8 chunks) x 512 threads.
//   Phase 1: each warp streams 8 [16,32] tr tiles, computes w row-sums into
//            SMEM (no global w tensor), gathers nc values.
//   Phase 2: 8 half-warps build the 8 level-0 matrices in SMEM; tail-chunk
//            block also exports raw tail w + level-0 matrices.
//   Phase 3: fold 8 -> 1 in place; store the 128-step chunk matrix.
// ---------------------------------------------------------------------------
__global__ __launch_bounds__(512) void semicrf_fused(
    const float* __restrict__ tr,
    const int*   __restrict__ tags,
    const int*   __restrict__ lens,
    float*       __restrict__ out)
{
    __shared__ float sA[8 * MSLOT];
    __shared__ int   sC[8];
    __shared__ float sNum[16];

    const int b    = blockIdx.x >> 3;
    const int c    = blockIdx.x & 7;
    const int tid  = threadIdx.x;
    const int warp = tid >> 5;
    const int lane = tid & 31;
    const int half = lane >> 4;
    const int hl   = lane & 15;
    const int sub  = lane >> 3;

    if (blockIdx.x == 0 && tid == 0) out[0] = 0.0f;

    const int len  = lens[b];
    const int m    = len >> 4;
    const int rem  = len & 15;
    const int qc   = m >> 3;
    const int tseg = m & 7;

    // ---- numerator gather: lane t (<8) handles tile warp*8+t ----
    {
        float ncv = 0.0f;
        if (lane < 8) {
            int e = c * 128 + warp * 8 + lane;
            if (e < len) {
                int tag = tags[b * S_ + e];
                ncv = tr[((size_t)(b * S_ + e)) * 512 + tag];
            }
        }
#pragma unroll
        for (int o = 4; o > 0; o >>= 1) ncv += __shfl_xor_sync(0xffffffffu, ncv, o);
        if (lane == 0) sNum[warp] = ncv;
    }

    // ---- phase 1: w row-sums for this warp's 8 tiles (2-tile pipeline) ----
    {
        const float4* tb = reinterpret_cast<const float4*>(tr)
                         + ((size_t)(b * S_ + c * 128 + warp * 8)) * 128;
        float4 cur[4], nxt[4];
#pragma unroll
        for (int i = 0; i < 4; i++) cur[i] = __ldcs(&tb[i * 32 + lane]);

#pragma unroll
        for (int t8 = 0; t8 < 8; t8++) {
            if (t8 < 7) {
#pragma unroll
                for (int i = 0; i < 4; i++)
                    nxt[i] = __ldcs(&tb[(t8 + 1) * 128 + i * 32 + lane]);
            }
            float rs[4];
#pragma unroll
            for (int i = 0; i < 4; i++) {
                float4 v = cur[i];
                float s = ex2f_(v.x * LOG2E) + ex2f_(v.y * LOG2E)
                        + ex2f_(v.z * LOG2E) + ex2f_(v.w * LOG2E);
                s += __shfl_xor_sync(0xffffffffu, s, 1);
                s += __shfl_xor_sync(0xffffffffu, s, 2);
                s += __shfl_xor_sync(0xffffffffu, s, 4);
                rs[i] = s;
            }
            const int tile = warp * 8 + t8;          // 0..127 within chunk
            if ((lane & 7) == 0) {
                float* wb = sA + (tile >> 4) * MSLOT + (tile & 15) * 16;
#pragma unroll
                for (int i = 0; i < 4; i++) wb[i * 4 + sub] = rs[i];
            }
#pragma unroll
            for (int i = 0; i < 4; i++) cur[i] = nxt[i];
        }
    }
    __syncthreads();

    // ---- numerator partial store (warp 5, otherwise idle in build) ----
    if (warp == 5) {
        float np = (lane < 16) ? sNum[lane] : 0.0f;
#pragma unroll
        for (int o = 8; o > 0; o >>= 1) np += __shfl_xor_sync(0xffffffffu, np, o);
        if (lane == 0) g_nump[b * 8 + c] = np;
    }
    // ---- tail w export (warp 4) ----
    if (warp == 4 && c == qc && rem > 0) {
        const float4* s4 = reinterpret_cast<const float4*>(sA + tseg * MSLOT);
        float4* d4 = reinterpret_cast<float4*>(g_tailw + b * 256);
        d4[lane]      = s4[lane];
        d4[lane + 32] = s4[lane + 32];
    }

    // ---- phase 2: build 1 level-0 matrix per half-warp (warps 0-3) ----
    float zzb[16];
    int   Cb2 = 0;
    const int segl = warp * 2 + half;
    if (warp < 4) {
        const float4* wv = reinterpret_cast<const float4*>(sA + segl * MSLOT);

#pragma unroll
        for (int k = 0; k < 16; k++) zzb[k] = (k == ((16 - hl) & 15)) ? 1.0f : 0.0f;

#pragma unroll
        for (int s = 0; s < 16; s++) {
            float4 rr0 = wv[s * 4 + 0], rr1 = wv[s * 4 + 1];
            float4 rr2 = wv[s * 4 + 2], rr3 = wv[s * 4 + 3];

            float p3 = zzb[(s - 15 + 32) & 15] * rr3.w;
            p3 = fmaf(zzb[(s - 14 + 32) & 15], rr3.z, p3);
            p3 = fmaf(zzb[(s - 13 + 32) & 15], rr3.y, p3);
            p3 = fmaf(zzb[(s - 12 + 32) & 15], rr3.x, p3);
            float p2 = zzb[(s - 11 + 32) & 15] * rr2.w;
            p2 = fmaf(zzb[(s - 10 + 32) & 15], rr2.z, p2);
            p2 = fmaf(zzb[(s -  9 + 32) & 15], rr2.y, p2);
            p2 = fmaf(zzb[(s -  8 + 32) & 15], rr2.x, p2);
            float p1 = zzb[(s -  7 + 32) & 15] * rr1.w;
            p1 = fmaf(zzb[(s -  6 + 32) & 15], rr1.z, p1);
            p1 = fmaf(zzb[(s -  5 + 32) & 15], rr1.y, p1);
            p1 = fmaf(zzb[(s -  4 + 32) & 15], rr1.x, p1);
            float p0 = zzb[(s -  3 + 32) & 15] * rr0.w;
            p0 = fmaf(zzb[(s -  2 + 32) & 15], rr0.z, p0);
            p0 = fmaf(zzb[(s -  1 + 32) & 15], rr0.y, p0);

            float zn = ((p3 + p2) + p1) + p0;
            zn = fmaf(zzb[s & 15], rr0.x, zn);
            zzb[(s + 1) & 15] = zn;

            if ((s & 3) == 3 && s != 15) {
                int ex = expo_(zn);
                ex = max(ex, __shfl_xor_sync(0xffffffffu, ex, 1, 16));
                ex = max(ex, __shfl_xor_sync(0xffffffffu, ex, 2, 16));
                ex = max(ex, __shfl_xor_sync(0xffffffffu, ex, 4, 16));
                ex = max(ex, __shfl_xor_sync(0xffffffffu, ex, 8, 16));
                int d = clampd_(ex - 127);
                Cb2 += d;
                float sc = __int_as_float((127 - d) << 23);
#pragma unroll
                for (int k2 = 0; k2 < 16; k2++) zzb[k2] *= sc;
            }
        }
        {   // final renorm: true matrix max -> ~2^0
            int ex = 0;
#pragma unroll
            for (int k = 0; k < 16; k++) ex = max(ex, expo_(zzb[k]));
            ex = max(ex, __shfl_xor_sync(0xffffffffu, ex, 1, 16));
            ex = max(ex, __shfl_xor_sync(0xffffffffu, ex, 2, 16));
            ex = max(ex, __shfl_xor_sync(0xffffffffu, ex, 4, 16));
            ex = max(ex, __shfl_xor_sync(0xffffffffu, ex, 8, 16));
            int d = clampd_(ex - 127);
            Cb2 += d;
            float sc = __int_as_float((127 - d) << 23);
#pragma unroll
            for (int k = 0; k < 16; k++) zzb[k] *= sc;
        }
    }
    __syncthreads();   // all reads of staged w (build + tail copy) complete

    if (warp < 4) {    // write matrices over the staged w
        float* slot = sA + segl * MSLOT;
#pragma unroll
        for (int i = 0; i < 16; i++) slot[i * AROW + hl] = zzb[(16 - i) & 15];
        if (hl == 0) sC[segl] = Cb2;

        if (c == qc && segl < tseg) {   // tail chunk: export level-0 matrices
            float* gd = g_A0t + ((size_t)b * 8 + segl) * 256;
#pragma unroll
            for (int i = 0; i < 16; i++) gd[i * 16 + hl] = zzb[(16 - i) & 15];
            if (hl == 0) g_C0t[b * 8 + segl] = Cb2;
        }
    }
    __syncthreads();

    // ---- phase 3: fold 8 -> 4 -> 2 -> 1, in place ----
    if (warp < 2) {
        int u = warp * 2 + half;
        matmul16(sA + (2 * u + 1) * MSLOT, sA + (2 * u) * MSLOT,
                 sA + (2 * u) * MSLOT, sC[2 * u + 1], sC[2 * u], &sC[2 * u], hl);
    }
    __syncthreads();
    if (warp == 0) {
        int u = half;
        matmul16(sA + (4 * u + 2) * MSLOT, sA + (4 * u) * MSLOT,
                 sA + (4 * u) * MSLOT, sC[4 * u + 2], sC[4 * u], &sC[4 * u], hl);
    }
    __syncthreads();
    if (warp == 0) {
        matmul16(sA + 4 * MSLOT, sA, sA, sC[4], sC[0], &sC[0], hl);
    }
    __syncthreads();

    if (tid < 256) {
        float* gp = g_P + ((size_t)b * 8 + c) * 256;
        gp[tid] = sA[(tid >> 4) * AROW + (tid & 15)];
        if (tid == 0) g_CP[b * 8 + c] = sC[0];
    }
}

// ---------------------------------------------------------------------------
// Kernel SCAN: 64 blocks x 128 threads. Stage <=15 matrices + tail w +
// numerator partials; warp 0 runs the short serial chain.
// ---------------------------------------------------------------------------
__global__ __launch_bounds__(128) void semicrf_scan(
    const int* __restrict__ lens,
    float*     __restrict__ out)
{
    __shared__ float sM[15 * MSLOT];
    __shared__ int   sCm[15];
    __shared__ float sTail[256];

    const int b    = blockIdx.x;
    const int tid  = threadIdx.x;
    const int warp = tid >> 5;
    const int lane = tid & 31;
    const int hl   = lane & 15;

    const int len  = lens[b];
    const int m    = len >> 4;
    const int rem  = len & 15;
    const int qc   = m >> 3;
    const int tseg = m & 7;
    const int n_m  = qc + tseg;

    // stage matrices (padded layout) — chunks first, then tail level-0s
    for (int idx = tid; idx < n_m * 256; idx += 128) {
        int j = idx >> 8, pos = idx & 255;
        const float* src = (j < qc)
            ? g_P   + ((size_t)b * 8 + j) * 256
            : g_A0t + ((size_t)b * 8 + (j - qc)) * 256;
        sM[j * MSLOT + (pos >> 4) * AROW + (pos & 15)] = src[pos];
    }
    if (tid < n_m)
        sCm[tid] = (tid < qc) ? g_CP[b * 8 + tid] : g_C0t[b * 8 + (tid - qc)];

    if (rem > 0 && tid < 64) {
        reinterpret_cast<float4*>(sTail)[tid] =
            reinterpret_cast<const float4*>(g_tailw + b * 256)[tid];
    }
    __syncthreads();

    if (warp == 0) {
        // numerator = sum of the 8 chunk partials
        float nt = (lane < 8) ? g_nump[b * 8 + lane] : 0.0f;
#pragma unroll
        for (int o = 4; o > 0; o >>= 1) nt += __shfl_xor_sync(0xffffffffu, nt, o);
        nt = __shfl_sync(0xffffffffu, nt, 0);

        float vf[16];
#pragma unroll
        for (int k = 0; k < 16; k++) vf[k] = (k == 0) ? 1.0f : 0.0f;
        int Cv = 0;

        for (int j = 0; j < n_m; j++)
            matvec16(sM + j * MSLOT, sCm[j], vf, Cv, hl);

        float den = ((float)Cv + lg2f_(vf[0])) * LN2;   // covers rem == 0
        if (rem > 0) {
            float zz[16];
#pragma unroll
            for (int j = 0; j < 16; j++) zz[j] = vf[(16 - j) & 15];
            const float4* wb = reinterpret_cast<const float4*>(sTail);
#pragma unroll
            for (int s2 = 0; s2 < 15; s2++) {
                if (s2 < rem) {
                    float4 rr0 = wb[s2 * 4 + 0], rr1 = wb[s2 * 4 + 1];
                    float4 rr2 = wb[s2 * 4 + 2], rr3 = wb[s2 * 4 + 3];

                    float p3 = zz[(s2 - 15 + 32) & 15] * rr3.w;
                    p3 = fmaf(zz[(s2 - 14 + 32) & 15], rr3.z, p3);
                    p3 = fmaf(zz[(s2 - 13 + 32) & 15], rr3.y, p3);
                    p3 = fmaf(zz[(s2 - 12 + 32) & 15], rr3.x, p3);
                    float p2 = zz[(s2 - 11 + 32) & 15] * rr2.w;
                    p2 = fmaf(zz[(s2 - 10 + 32) & 15], rr2.z, p2);
                    p2 = fmaf(zz[(s2 -  9 + 32) & 15], rr2.y, p2);
                    p2 = fmaf(zz[(s2 -  8 + 32) & 15], rr2.x, p2);
                    float p1 = zz[(s2 -  7 + 32) & 15] * rr1.w;
                    p1 = fmaf(zz[(s2 -  6 + 32) & 15], rr1.z, p1);
                    p1 = fmaf(zz[(s2 -  5 + 32) & 15], rr1.y, p1);
                    p1 = fmaf(zz[(s2 -  4 + 32) & 15], rr1.x, p1);
                    float p0 = zz[(s2 -  3 + 32) & 15] * rr0.w;
                    p0 = fmaf(zz[(s2 -  2 + 32) & 15], rr0.z, p0);
                    p0 = fmaf(zz[(s2 -  1 + 32) & 15], rr0.y, p0);

                    float zn = ((p3 + p2) + p1) + p0;
                    zn = fmaf(zz[s2 & 15], rr0.x, zn);

                    if (s2 == rem - 1) den = ((float)Cv + lg2f_(zn)) * LN2;

                    zz[(s2 + 1) & 15] = zn;

                    if ((s2 & 1) == 1) {   // uniform renorm (all lanes identical)
                        int d2 = clampd_(expo_(zn) - 127);
                        Cv += d2;
                        float sc2 = __int_as_float((127 - d2) << 23);
#pragma unroll
                        for (int k2 = 0; k2 < 16; k2++) zz[k2] *= sc2;
                    }
                }
            }
        }

        if (lane == 0) atomicAdd(out, den - nt);
    }
}

// ---------------------------------------------------------------------------
extern "C" void kernel_launch(void* const* d_in, const int* in_sizes, int n_in,
                              void* d_out, int out_size)
{
    const float* tr   = (const float*)d_in[0];   // [B,S,L,T] f32
    const int*   tags = (const int*)  d_in[1];   // [B,S] i32
    const int*   lens = (const int*)  d_in[2];   // [B] i32
    float*       out  = (float*)d_out;           // scalar f32

    semicrf_fused<<<512, 512>>>(tr, tags, lens, out);   // stream tr + build chunks
    semicrf_scan<<<64, 128>>>(lens, out);               // short serial chain
}

// round 8
// speedup vs baseline: 1.6082x; 1.6082x over previous
#include <cuda_runtime.h>

// Problem shape (fixed for this instance)
#define B_ 64
#define S_ 1024
#define L_ 16
#define T_ 32
#define AROW 20            // padded row stride (floats) for the 16x16 matrices
#define MSLOT (AROW * 16)  // 320 floats per matrix slot

#define LOG2E 1.4426950408889634f
#define LN2   0.6931471805599453f

// Scratch (static __device__ arrays — allocation-free per harness rules)
__device__ __align__(16) float g_P   [B_ * 8 * 256];   // 128-step chunk matrices
__device__ __align__(16) float g_A0t [B_ * 8 * 256];   // level-0 matrices of the tail chunk
__device__ __align__(16) float g_tailw[B_ * 256];      // raw w rows for the <16-step tail
__device__             float g_nump[B_ * 8];           // per-(b,chunk) numerator partials
__device__             int   g_CP  [B_ * 8];           // chunk scale exponents
__device__             int   g_C0t [B_ * 8];           // tail-chunk level-0 exponents

__device__ __forceinline__ float ex2f_(float x) {
    float r; asm("ex2.approx.f32 %0, %1;" : "=f"(r) : "f"(x)); return r;
}
__device__ __forceinline__ float lg2f_(float x) {
    float r; asm("lg2.approx.f32 %0, %1;" : "=f"(r) : "f"(x)); return r;
}
__device__ __forceinline__ int clampd_(int d) {
    return d < -120 ? -120 : (d > 120 ? 120 : d);
}
__device__ __forceinline__ int expo_(float x) {
    return (__float_as_int(x) >> 23) & 255;
}

// ---------------------------------------------------------------------------
// 16x16 matrix product D = Am * Bm, one column (hl) per 16-lane group.
// Row-major, row stride AROW. Result max-normalized to ~2^0. D may alias Bm.
// Warp-uniform caller required (full-mask shuffles).
// ---------------------------------------------------------------------------
__device__ __forceinline__ void matmul16(
    const float* Am, const float* Bm, float* Dst,
    int Ca, int Cb, int* Cdst, int hl)
{
    float bc[16];
#pragma unroll
    for (int k = 0; k < 16; k++) bc[k] = Bm[k * AROW + hl];

    float r[16];
#pragma unroll
    for (int i = 0; i < 16; i++) {
        const float4* ar = reinterpret_cast<const float4*>(Am + i * AROW);
        float4 a0 = ar[0], a1 = ar[1], a2 = ar[2], a3 = ar[3];
        float s0 = a0.x * bc[0];
        s0 = fmaf(a0.y, bc[1], s0); s0 = fmaf(a0.z, bc[2], s0); s0 = fmaf(a0.w, bc[3], s0);
        float s1 = a1.x * bc[4];
        s1 = fmaf(a1.y, bc[5], s1); s1 = fmaf(a1.z, bc[6], s1); s1 = fmaf(a1.w, bc[7], s1);
        float s2 = a2.x * bc[8];
        s2 = fmaf(a2.y, bc[9], s2); s2 = fmaf(a2.z, bc[10], s2); s2 = fmaf(a2.w, bc[11], s2);
        float s3 = a3.x * bc[12];
        s3 = fmaf(a3.y, bc[13], s3); s3 = fmaf(a3.z, bc[14], s3); s3 = fmaf(a3.w, bc[15], s3);
        r[i] = (s0 + s1) + (s2 + s3);
    }

    int ex = 0;
#pragma unroll
    for (int i = 0; i < 16; i++) ex = max(ex, expo_(r[i]));
    ex = max(ex, __shfl_xor_sync(0xffffffffu, ex, 1, 16));
    ex = max(ex, __shfl_xor_sync(0xffffffffu, ex, 2, 16));
    ex = max(ex, __shfl_xor_sync(0xffffffffu, ex, 4, 16));
    ex = max(ex, __shfl_xor_sync(0xffffffffu, ex, 8, 16));
    int d = clampd_(ex - 127);
    float sc = __int_as_float((127 - d) << 23);
#pragma unroll
    for (int i = 0; i < 16; i++) Dst[i * AROW + hl] = r[i] * sc;
    if (hl == 0) *Cdst = Ca + Cb + d;
}

// Serial matvec: vf <- normalize(M * vf); row hl per lane, vf replicated on
// all 32 lanes (halves mirror via width-16 shfl). Warp-uniform caller.
__device__ __forceinline__ void matvec16(
    const float* __restrict__ M, int Cm, float* vf, int& Cv, int hl)
{
    const float4* rp = reinterpret_cast<const float4*>(M + hl * AROW);
    float4 c0 = rp[0], c1 = rp[1], c2 = rp[2], c3 = rp[3];
    float a0 = c0.x * vf[0];
    a0 = fmaf(c0.y, vf[1], a0); a0 = fmaf(c0.z, vf[2], a0); a0 = fmaf(c0.w, vf[3], a0);
    float a1 = c1.x * vf[4];
    a1 = fmaf(c1.y, vf[5], a1); a1 = fmaf(c1.z, vf[6], a1); a1 = fmaf(c1.w, vf[7], a1);
    float a2 = c2.x * vf[8];
    a2 = fmaf(c2.y, vf[9], a2); a2 = fmaf(c2.z, vf[10], a2); a2 = fmaf(c2.w, vf[11], a2);
    float a3 = c3.x * vf[12];
    a3 = fmaf(c3.y, vf[13], a3); a3 = fmaf(c3.z, vf[14], a3); a3 = fmaf(c3.w, vf[15], a3);
    float s = (a0 + a1) + (a2 + a3);
#pragma unroll
    for (int k = 0; k < 16; k++) vf[k] = __shfl_sync(0xffffffffu, s, k, 16);
    int ex = 0;
#pragma unroll
    for (int k = 0; k < 16; k++) ex = max(ex, expo_(vf[k]));
    int d = clampd_(ex - 127);
    Cv += d + Cm;
    float sc = __int_as_float((127 - d) << 23);
#pragma unroll
    for (int k = 0; k < 16; k++) vf[k] *= sc;
}

// ---------------------------------------------------------------------------
// Kernel FUSED: 512 blocks (64 batches x 8 chunks) x 512 threads.
// Length-aware: blocks past the needed range exit without touching tr.
// All intra-warp collectives are warp-uniform (deadlock-safe).
// ---------------------------------------------------------------------------
__global__ __launch_bounds__(512) void semicrf_fused(
    const float* __restrict__ tr,
    const int*   __restrict__ tags,
    const int*   __restrict__ lens,
    float*       __restrict__ out)
{
    __shared__ float sA[8 * MSLOT];
    __shared__ int   sC[8];
    __shared__ float sNum[16];

    const int b    = blockIdx.x >> 3;
    const int c    = blockIdx.x & 7;
    const int tid  = threadIdx.x;
    const int warp = tid >> 5;
    const int lane = tid & 31;
    const int half = lane >> 4;
    const int hl   = lane & 15;
    const int sub  = lane >> 3;

    if (blockIdx.x == 0 && tid == 0) out[0] = 0.0f;

    const int len  = lens[b];
    const int m    = len >> 4;
    const int rem  = len & 15;
    const int qc   = m >> 3;
    const int tseg = m & 7;

    const bool full  = (c < qc);
    const bool tailb = (c == qc);
    // number of tiles (time steps) this block must process
    const int nt = full ? 128 : (tailb ? (tseg * 16 + (rem > 0 ? 16 : 0)) : 0);

    // ---- numerator gather: lane t (<8) handles tile warp*8+t ----
    {
        float ncv = 0.0f;
        if (lane < 8) {
            int e = c * 128 + warp * 8 + lane;
            if (e < len) {
                int tag = tags[b * S_ + e];
                ncv = tr[((size_t)(b * S_ + e)) * 512 + tag];
            }
        }
#pragma unroll
        for (int o = 4; o > 0; o >>= 1) ncv += __shfl_xor_sync(0xffffffffu, ncv, o);
        if (lane == 0) sNum[warp] = ncv;
    }

    if (nt == 0) {   // block-uniform early exit
        __syncthreads();
        if (warp == 0 && tailb) {   // record the (zero) numerator partial
            float np = (lane < 16) ? sNum[lane] : 0.0f;
#pragma unroll
            for (int o = 8; o > 0; o >>= 1) np += __shfl_xor_sync(0xffffffffu, np, o);
            if (lane == 0) g_nump[b * 8 + c] = np;
        }
        return;
    }

    // ---- zero-fill unstaged segment slots in tail blocks (avoid garbage) ----
    if (!full) {
        for (int i = tid; i < 8 * MSLOT; i += 512) sA[i] = 0.0f;
        __syncthreads();
    }

    // ---- phase 1: w row-sums for this warp's needed tiles (pipelined) ----
    {
        const float4* tb = reinterpret_cast<const float4*>(tr)
                         + ((size_t)(b * S_ + c * 128 + warp * 8)) * 128;
        const int base = warp * 8;
        float4 cur[4], nxt[4];
        if (base < nt) {
#pragma unroll
            for (int i = 0; i < 4; i++) cur[i] = __ldcs(&tb[i * 32 + lane]);
        }
#pragma unroll
        for (int t8 = 0; t8 < 8; t8++) {
            const int tile = base + t8;          // warp-uniform
            if (tile >= nt) break;
            if (tile + 1 < nt) {
#pragma unroll
                for (int i = 0; i < 4; i++)
                    nxt[i] = __ldcs(&tb[(t8 + 1) * 128 + i * 32 + lane]);
            }
            float rs[4];
#pragma unroll
            for (int i = 0; i < 4; i++) {
                float4 v = cur[i];
                float s = ex2f_(v.x * LOG2E) + ex2f_(v.y * LOG2E)
                        + ex2f_(v.z * LOG2E) + ex2f_(v.w * LOG2E);
                s += __shfl_xor_sync(0xffffffffu, s, 1);
                s += __shfl_xor_sync(0xffffffffu, s, 2);
                s += __shfl_xor_sync(0xffffffffu, s, 4);
                rs[i] = s;
            }
            if ((lane & 7) == 0) {
                float* wb = sA + (tile >> 4) * MSLOT + (tile & 15) * 16;
#pragma unroll
                for (int i = 0; i < 4; i++) wb[i * 4 + sub] = rs[i];
            }
#pragma unroll
            for (int i = 0; i < 4; i++) cur[i] = nxt[i];
        }
    }
    __syncthreads();

    // ---- numerator partial store (warp 5) ----
    if (warp == 5) {
        float np = (lane < 16) ? sNum[lane] : 0.0f;
#pragma unroll
        for (int o = 8; o > 0; o >>= 1) np += __shfl_xor_sync(0xffffffffu, np, o);
        if (lane == 0) g_nump[b * 8 + c] = np;
    }
    // ---- tail w export (warp 4) ----
    if (warp == 4 && tailb && rem > 0) {
        const float4* s4 = reinterpret_cast<const float4*>(sA + tseg * MSLOT);
        float4* d4 = reinterpret_cast<float4*>(g_tailw + b * 256);
        d4[lane]      = s4[lane];
        d4[lane + 32] = s4[lane + 32];
    }

    // ---- phase 2: build level-0 matrices (warps 0-3, WARP-UNIFORM) ----
    // Tail blocks build all 8 too (unstaged slots are zeros — harmless);
    // only the needed ones are stored.
    const int segl = warp * 2 + half;
    float zzb[16];
    int   Cb2 = 0;
    if (warp < 4) {
        const float4* wv = reinterpret_cast<const float4*>(sA + segl * MSLOT);

#pragma unroll
        for (int k = 0; k < 16; k++) zzb[k] = (k == ((16 - hl) & 15)) ? 1.0f : 0.0f;

#pragma unroll
        for (int s = 0; s < 16; s++) {
            float4 rr0 = wv[s * 4 + 0], rr1 = wv[s * 4 + 1];
            float4 rr2 = wv[s * 4 + 2], rr3 = wv[s * 4 + 3];

            float p3 = zzb[(s - 15 + 32) & 15] * rr3.w;
            p3 = fmaf(zzb[(s - 14 + 32) & 15], rr3.z, p3);
            p3 = fmaf(zzb[(s - 13 + 32) & 15], rr3.y, p3);
            p3 = fmaf(zzb[(s - 12 + 32) & 15], rr3.x, p3);
            float p2 = zzb[(s - 11 + 32) & 15] * rr2.w;
            p2 = fmaf(zzb[(s - 10 + 32) & 15], rr2.z, p2);
            p2 = fmaf(zzb[(s -  9 + 32) & 15], rr2.y, p2);
            p2 = fmaf(zzb[(s -  8 + 32) & 15], rr2.x, p2);
            float p1 = zzb[(s -  7 + 32) & 15] * rr1.w;
            p1 = fmaf(zzb[(s -  6 + 32) & 15], rr1.z, p1);
            p1 = fmaf(zzb[(s -  5 + 32) & 15], rr1.y, p1);
            p1 = fmaf(zzb[(s -  4 + 32) & 15], rr1.x, p1);
            float p0 = zzb[(s -  3 + 32) & 15] * rr0.w;
            p0 = fmaf(zzb[(s -  2 + 32) & 15], rr0.z, p0);
            p0 = fmaf(zzb[(s -  1 + 32) & 15], rr0.y, p0);

            float zn = ((p3 + p2) + p1) + p0;
            zn = fmaf(zzb[s & 15], rr0.x, zn);
            zzb[(s + 1) & 15] = zn;

            if ((s & 3) == 3 && s != 15) {
                int ex = expo_(zn);
                ex = max(ex, __shfl_xor_sync(0xffffffffu, ex, 1, 16));
                ex = max(ex, __shfl_xor_sync(0xffffffffu, ex, 2, 16));
                ex = max(ex, __shfl_xor_sync(0xffffffffu, ex, 4, 16));
                ex = max(ex, __shfl_xor_sync(0xffffffffu, ex, 8, 16));
                int d = clampd_(ex - 127);
                Cb2 += d;
                float sc = __int_as_float((127 - d) << 23);
#pragma unroll
                for (int k2 = 0; k2 < 16; k2++) zzb[k2] *= sc;
            }
        }
        {   // final renorm: true matrix max -> ~2^0
            int ex = 0;
#pragma unroll
            for (int k = 0; k < 16; k++) ex = max(ex, expo_(zzb[k]));
            ex = max(ex, __shfl_xor_sync(0xffffffffu, ex, 1, 16));
            ex = max(ex, __shfl_xor_sync(0xffffffffu, ex, 2, 16));
            ex = max(ex, __shfl_xor_sync(0xffffffffu, ex, 4, 16));
            ex = max(ex, __shfl_xor_sync(0xffffffffu, ex, 8, 16));
            int d = clampd_(ex - 127);
            Cb2 += d;
            float sc = __int_as_float((127 - d) << 23);
#pragma unroll
            for (int k = 0; k < 16; k++) zzb[k] *= sc;
        }
    }
    __syncthreads();   // all reads of staged w (build + tail copy) complete

    if (warp < 4) {
        if (full) {        // keep in SMEM for the fold
            float* slot = sA + segl * MSLOT;
#pragma unroll
            for (int i = 0; i < 16; i++) slot[i * AROW + hl] = zzb[(16 - i) & 15];
            if (hl == 0) sC[segl] = Cb2;
        } else if (segl < tseg) {   // tail chunk: export only needed level-0s
            float* gd = g_A0t + ((size_t)b * 8 + segl) * 256;
#pragma unroll
            for (int i = 0; i < 16; i++) gd[i * 16 + hl] = zzb[(16 - i) & 15];
            if (hl == 0) g_C0t[b * 8 + segl] = Cb2;
        }
    }

    if (!full) return;     // block-uniform: tail blocks are done

    __syncthreads();

    // ---- phase 3: fold 8 -> 4 -> 2 -> 1, in place ----
    if (warp < 2) {
        int u = warp * 2 + half;
        matmul16(sA + (2 * u + 1) * MSLOT, sA + (2 * u) * MSLOT,
                 sA + (2 * u) * MSLOT, sC[2 * u + 1], sC[2 * u], &sC[2 * u], hl);
    }
    __syncthreads();
    if (warp == 0) {
        int u = half;
        matmul16(sA + (4 * u + 2) * MSLOT, sA + (4 * u) * MSLOT,
                 sA + (4 * u) * MSLOT, sC[4 * u + 2], sC[4 * u], &sC[4 * u], hl);
    }
    __syncthreads();
    if (warp == 0) {
        matmul16(sA + 4 * MSLOT, sA, sA, sC[4], sC[0], &sC[0], hl);
    }
    __syncthreads();

    if (tid < 256) {
        float* gp = g_P + ((size_t)b * 8 + c) * 256;
        gp[tid] = sA[(tid >> 4) * AROW + (tid & 15)];
        if (tid == 0) g_CP[b * 8 + c] = sC[0];
    }
}

// ---------------------------------------------------------------------------
// Kernel SCAN: 64 blocks x 256 threads. Register-batched staging (15
// independent LDGs in flight per thread), then warp 0 runs the short chain.
// ---------------------------------------------------------------------------
__global__ __launch_bounds__(256) void semicrf_scan(
    const int* __restrict__ lens,
    float*     __restrict__ out)
{
    __shared__ float sM[15 * MSLOT];
    __shared__ int   sCm[15];
    __shared__ float sTail[256];

    const int b    = blockIdx.x;
    const int tid  = threadIdx.x;
    const int warp = tid >> 5;
    const int lane = tid & 31;
    const int hl   = lane & 15;

    const int len  = lens[b];
    const int m    = len >> 4;
    const int rem  = len & 15;
    const int qc   = m >> 3;
    const int tseg = m & 7;
    const int n_m  = qc + tseg;
    const int tot  = n_m * 256;

    // stage matrices: 15 independent predicated loads per thread, then store
    {
        float v[15];
#pragma unroll
        for (int r = 0; r < 15; r++) {
            int idx = tid + r * 256;
            float x = 0.0f;
            if (idx < tot) {
                int j = idx >> 8, pos = idx & 255;
                const float* src = (j < qc)
                    ? g_P   + ((size_t)b * 8 + j) * 256
                    : g_A0t + ((size_t)b * 8 + (j - qc)) * 256;
                x = src[pos];
            }
            v[r] = x;
        }
#pragma unroll
        for (int r = 0; r < 15; r++) {
            int idx = tid + r * 256;
            if (idx < tot) {
                int j = idx >> 8, pos = idx & 255;
                sM[j * MSLOT + (pos >> 4) * AROW + (pos & 15)] = v[r];
            }
        }
    }
    if (tid < n_m)
        sCm[tid] = (tid < qc) ? g_CP[b * 8 + tid] : g_C0t[b * 8 + (tid - qc)];

    if (rem > 0 && tid < 64) {
        reinterpret_cast<float4*>(sTail)[tid] =
            reinterpret_cast<const float4*>(g_tailw + b * 256)[tid];
    }
    __syncthreads();

    if (warp == 0) {
        // numerator = sum of partials for chunks 0..qc (others never written)
        float nt = (lane < 8 && lane <= qc) ? g_nump[b * 8 + lane] : 0.0f;
#pragma unroll
        for (int o = 4; o > 0; o >>= 1) nt += __shfl_xor_sync(0xffffffffu, nt, o);
        nt = __shfl_sync(0xffffffffu, nt, 0);

        float vf[16];
#pragma unroll
        for (int k = 0; k < 16; k++) vf[k] = (k == 0) ? 1.0f : 0.0f;
        int Cv = 0;

        for (int j = 0; j < n_m; j++)
            matvec16(sM + j * MSLOT, sCm[j], vf, Cv, hl);

        float den = ((float)Cv + lg2f_(vf[0])) * LN2;   // covers rem == 0
        if (rem > 0) {
            float zz[16];
#pragma unroll
            for (int j = 0; j < 16; j++) zz[j] = vf[(16 - j) & 15];
            const float4* wb = reinterpret_cast<const float4*>(sTail);
#pragma unroll
            for (int s2 = 0; s2 < 15; s2++) {
                if (s2 < rem) {
                    float4 rr0 = wb[s2 * 4 + 0], rr1 = wb[s2 * 4 + 1];
                    float4 rr2 = wb[s2 * 4 + 2], rr3 = wb[s2 * 4 + 3];

                    float p3 = zz[(s2 - 15 + 32) & 15] * rr3.w;
                    p3 = fmaf(zz[(s2 - 14 + 32) & 15], rr3.z, p3);
                    p3 = fmaf(zz[(s2 - 13 + 32) & 15], rr3.y, p3);
                    p3 = fmaf(zz[(s2 - 12 + 32) & 15], rr3.x, p3);
                    float p2 = zz[(s2 - 11 + 32) & 15] * rr2.w;
                    p2 = fmaf(zz[(s2 - 10 + 32) & 15], rr2.z, p2);
                    p2 = fmaf(zz[(s2 -  9 + 32) & 15], rr2.y, p2);
                    p2 = fmaf(zz[(s2 -  8 + 32) & 15], rr2.x, p2);
                    float p1 = zz[(s2 -  7 + 32) & 15] * rr1.w;
                    p1 = fmaf(zz[(s2 -  6 + 32) & 15], rr1.z, p1);
                    p1 = fmaf(zz[(s2 -  5 + 32) & 15], rr1.y, p1);
                    p1 = fmaf(zz[(s2 -  4 + 32) & 15], rr1.x, p1);
                    float p0 = zz[(s2 -  3 + 32) & 15] * rr0.w;
                    p0 = fmaf(zz[(s2 -  2 + 32) & 15], rr0.z, p0);
                    p0 = fmaf(zz[(s2 -  1 + 32) & 15], rr0.y, p0);

                    float zn = ((p3 + p2) + p1) + p0;
                    zn = fmaf(zz[s2 & 15], rr0.x, zn);

                    if (s2 == rem - 1) den = ((float)Cv + lg2f_(zn)) * LN2;

                    zz[(s2 + 1) & 15] = zn;

                    if ((s2 & 1) == 1) {   // uniform renorm (all lanes identical)
                        int d2 = clampd_(expo_(zn) - 127);
                        Cv += d2;
                        float sc2 = __int_as_float((127 - d2) << 23);
#pragma unroll
                        for (int k2 = 0; k2 < 16; k2++) zz[k2] *= sc2;
                    }
                }
            }
        }

        if (lane == 0) atomicAdd(out, den - nt);
    }
}

// ---------------------------------------------------------------------------
extern "C" void kernel_launch(void* const* d_in, const int* in_sizes, int n_in,
                              void* d_out, int out_size)
{
    const float* tr   = (const float*)d_in[0];   // [B,S,L,T] f32
    const int*   tags = (const int*)  d_in[1];   // [B,S] i32
    const int*   lens = (const int*)  d_in[2];   // [B] i32
    float*       out  = (float*)d_out;           // scalar f32

    semicrf_fused<<<512, 512>>>(tr, tags, lens, out);   // length-aware stream + fold
    semicrf_scan<<<64, 256>>>(lens, out);               // short serial chain
}